// round 16
// baseline (speedup 1.0000x reference)
#include <cuda_runtime.h>
#include <cuda_bf16.h>
#include <cstdint>

// Problem constants
#define B_ 8
#define S_ 1024
#define E_ 1024
#define H_ 16
#define D_ 64
#define ROWS (B_ * S_)          // 8192
#define GROUPS (B_ * H_)        // 128
#define FULL 0xffffffffu

// Scratch (device globals; allocation is forbidden)
__device__ uint32_t g_qb[ROWS * E_];     // Q, tf32 bits, A-frag per (group,qt)
__device__ uint32_t g_kb[ROWS * E_];     // K, tf32 bits, B-frag per (group,chunk)
__device__ uint32_t g_vb[ROWS * E_];     // V, tf32 bits, B-frag per (group,chunk)
__device__ uint32_t g_attb[ROWS * E_];   // attention out, tf32 bits, A-frag (GEMM)
__device__ uint32_t g_x[ROWS * E_];      // hidden_states, tf32 bits, A-frag (GEMM)
__device__ uint32_t g_wt[4 * E_ * E_];   // weights, tf32 bits, B-frag (GEMM)

// scale * log2(e) = (1/32) * 1.4426950408889634
#define QSCALE 0.04508422f

__device__ __forceinline__ uint32_t f2tf(float x) {
    uint32_t u;
    asm("cvt.rna.tf32.f32 %0, %1;" : "=r"(u) : "f"(x));
    return u;
}
__device__ __forceinline__ float ex2f(float x) {
    float r;
    asm("ex2.approx.f32 %0, %1;" : "=f"(r) : "f"(x));
    return r;
}

__device__ __forceinline__ void mma_tf32(float c[4], uint32_t a0, uint32_t a1,
                                         uint32_t a2, uint32_t a3,
                                         uint32_t b0, uint32_t b1) {
    asm volatile(
        "mma.sync.aligned.m16n8k8.row.col.f32.tf32.tf32.f32 "
        "{%0,%1,%2,%3},{%4,%5,%6,%7},{%8,%9},{%0,%1,%2,%3};"
        : "+f"(c[0]), "+f"(c[1]), "+f"(c[2]), "+f"(c[3])
        : "r"(a0), "r"(a1), "r"(a2), "r"(a3), "r"(b0), "r"(b1));
}

__device__ __forceinline__ uint32_t smem_u32(const void* p) {
    uint32_t a;
    asm("{ .reg .u64 t; cvta.to.shared.u64 t, %1; cvt.u32.u64 %0, t; }"
        : "=r"(a) : "l"(p));
    return a;
}

__device__ __forceinline__ void cp16(uint32_t dst, const void* src) {
    asm volatile("cp.async.cg.shared.global [%0], [%1], 16;"
                 :: "r"(dst), "l"(src));
}
#define CPCOMMIT() asm volatile("cp.async.commit_group;" ::: "memory")
#define CPWAIT(n)  asm volatile("cp.async.wait_group %0;" :: "n"(n) : "memory")

// ===========================================================================
// GEMM fragment-order layouts (words of tf32 bits)  — unchanged from r13/14
// ===========================================================================
__device__ __forceinline__ size_t a_addr(int m, int k) {
    return (size_t)((m >> 7) * 64 + (k >> 4)) * 2048
         + ((k >> 3) & 1) * 1024 + ((m >> 4) & 7) * 128
         + ((m & 7) * 4 + (k & 3)) * 4 + ((k >> 2) & 1) * 2 + ((m >> 3) & 1);
}
__device__ __forceinline__ size_t b_addr(int n, int k) {
    return (size_t)((n >> 7) * 64 + (k >> 4)) * 2048
         + ((n >> 3) & 15) * 128
         + ((n & 7) * 4 + (k & 3)) * 4 + ((k >> 3) & 1) * 2 + ((k >> 2) & 1);
}

// ===========================================================================
// Attention fragment layouts. Matrix row m (= b*1024+s), col n (= e):
//   group g = m>>6 ; s2 = (m&63)*16 + (n>>6) ; d = n&63
// Q  (A-frag):  g*65536 + qt*1024 + kd*128 + lane*4 + slot
//               qt=s2>>4, r16=s2&15, gid=r16&7, rh=r16>>3,
//               kd=d>>3, dm=d&7, tl=dm&3, ah=dm>>2, lane=gid*4+tl, slot=ah*2+rh
// K  (B-frag of QK): g*65536 + c*4096 + jt*512 + (kd>>1)*128 + lane*4
//               + (kd&1)*2 + half ;  c=s2>>6, kv=s2&63, jt=kv>>3, gid=kv&7,
//               kd=d>>3, dm=d&7, tl=dm&3, half=dm>>2, lane=gid*4+tl
// V  (B-frag of PV): g*65536 + c*4096 + jd*512 + (kk>>1)*128 + lane*4
//               + (kk&1)*2 + half ;  c=s2>>6, kv=s2&63, kk=kv>>3, km=kv&7,
//               tl=km&3, half=km>>2, jd=d>>3, gid=d&7, lane=gid*4+tl
// ===========================================================================
__device__ __forceinline__ size_t q_addr(int m, int n) {
    const int g = m >> 6, s2 = (m & 63) * 16 + (n >> 6), d = n & 63;
    const int qt = s2 >> 4, r16 = s2 & 15, gid = r16 & 7, rh = r16 >> 3;
    const int kd = d >> 3, dm = d & 7, tl = dm & 3, ah = dm >> 2;
    return (size_t)g * 65536 + qt * 1024 + kd * 128 + (gid * 4 + tl) * 4
         + ah * 2 + rh;
}
__device__ __forceinline__ size_t k_addr(int m, int n) {
    const int g = m >> 6, s2 = (m & 63) * 16 + (n >> 6), d = n & 63;
    const int c = s2 >> 6, kv = s2 & 63, jt = kv >> 3, gid = kv & 7;
    const int kd = d >> 3, dm = d & 7, tl = dm & 3, half = dm >> 2;
    return (size_t)g * 65536 + c * 4096 + jt * 512 + (kd >> 1) * 128
         + (gid * 4 + tl) * 4 + (kd & 1) * 2 + half;
}
__device__ __forceinline__ size_t v_addr(int m, int n) {
    const int g = m >> 6, s2 = (m & 63) * 16 + (n >> 6), d = n & 63;
    const int c = s2 >> 6, kv = s2 & 63, kk = kv >> 3, km = kv & 7;
    const int tl = km & 3, half = km >> 2, jd = d >> 3, gid = d & 7;
    return (size_t)g * 65536 + c * 4096 + jd * 512 + (kk >> 1) * 128
         + (gid * 4 + tl) * 4 + (kk & 1) * 2 + half;
}

// ===========================================================================
// Weight W[k][n] -> B-frag layout (tf32). grid (1024, 1, 4), block 256.
// ===========================================================================
__global__ __launch_bounds__(256) void transpose_w(
    const float* __restrict__ w0, const float* __restrict__ w1,
    const float* __restrict__ w2, const float* __restrict__ w3,
    uint32_t* __restrict__ outb)
{
    const float* src = (blockIdx.z == 0) ? w0 : (blockIdx.z == 1) ? w1
                     : (blockIdx.z == 2) ? w2 : w3;
    uint32_t* dst = outb + (size_t)blockIdx.z * E_ * E_;

    const int idx = blockIdx.x * 256 + threadIdx.x;
    const int k  = idx >> 8;
    const int n4 = (idx & 255) * 4;
    float4 v = *(const float4*)(src + (size_t)k * E_ + n4);
    dst[b_addr(n4 + 0, k)] = f2tf(v.x);
    dst[b_addr(n4 + 1, k)] = f2tf(v.y);
    dst[b_addr(n4 + 2, k)] = f2tf(v.z);
    dst[b_addr(n4 + 3, k)] = f2tf(v.w);
}

// ===========================================================================
// hidden_states -> A-frag layout (tf32). grid (8192), block 256.
// ===========================================================================
__global__ __launch_bounds__(256) void convert_x(
    const float* __restrict__ in, uint32_t* __restrict__ out)
{
    const int idx = blockIdx.x * 256 + threadIdx.x;
    const int m  = idx >> 8;
    const int k4 = (idx & 255) * 4;
    float4 v = *(const float4*)(in + (size_t)m * E_ + k4);
    out[a_addr(m, k4 + 0)] = f2tf(v.x);
    out[a_addr(m, k4 + 1)] = f2tf(v.y);
    out[a_addr(m, k4 + 2)] = f2tf(v.z);
    out[a_addr(m, k4 + 3)] = f2tf(v.w);
}

// ===========================================================================
// Pipelined TF32 mma.sync GEMM, fragment-order operands (r13 proven).
// otf=1: bz selects output mode 1=Q/2=K/3=V (attn frag scatter, Q pre-scaled)
// otf=0: fp32 row-major + bias.
// grid (8, 64, nmat)
// ===========================================================================
#define CHW 2048
#define STW (2 * CHW)
#define GSMEM (4 * STW * 4)      // 65536 bytes

__global__ __launch_bounds__(256, 2) void gemm_tc32(
    const uint32_t* __restrict__ A, const uint32_t* __restrict__ Bt_base,
    const float* __restrict__ bias, int otf,
    float* __restrict__ C0, float* __restrict__ C1, float* __restrict__ C2)
{
    extern __shared__ uint32_t sm[];
    const uint32_t sb = smem_u32(sm);

    const int tid  = threadIdx.x;
    const int lane = tid & 31;
    const int wid  = tid >> 5;
    const int wm   = wid >> 2;
    const int wn   = wid & 3;
    const int gid  = lane >> 2;
    const int tig  = lane & 3;

    const int bx = blockIdx.x, by = blockIdx.y, bz = blockIdx.z;
    float* C = (bz == 0) ? C0 : (bz == 1) ? C1 : C2;
    const int mode = otf ? (bz + 1) : 0;

    const uint32_t* Apan = A + (size_t)by * 64 * CHW;
    const uint32_t* Bpan = Bt_base + (size_t)bz * E_ * E_ + (size_t)bx * 64 * CHW;

    float acc[4][4][4];
    #pragma unroll
    for (int i = 0; i < 4; i++)
        #pragma unroll
        for (int j = 0; j < 4; j++)
            #pragma unroll
            for (int f = 0; f < 4; f++) acc[i][j][f] = 0.0f;

    const uint32_t dA = sb + (uint32_t)tid * 32;
    const uint32_t dB = dA + CHW * 4;

    #pragma unroll
    for (int s = 0; s < 3; s++) {
        const uint32_t stoff = (uint32_t)(s * STW) * 4;
        const uint32_t* ag = Apan + (size_t)s * CHW + tid * 8;
        const uint32_t* bg = Bpan + (size_t)s * CHW + tid * 8;
        cp16(dA + stoff,      ag);
        cp16(dA + stoff + 16, ag + 4);
        cp16(dB + stoff,      bg);
        cp16(dB + stoff + 16, bg + 4);
        CPCOMMIT();
    }

    for (int c = 0; c < 64; c++) {
        CPWAIT(2);
        __syncthreads();

        if (c + 3 < 64) {
            const uint32_t stoff = (uint32_t)(((c + 3) & 3) * STW) * 4;
            const uint32_t* ag = Apan + (size_t)(c + 3) * CHW + tid * 8;
            const uint32_t* bg = Bpan + (size_t)(c + 3) * CHW + tid * 8;
            cp16(dA + stoff,      ag);
            cp16(dA + stoff + 16, ag + 4);
            cp16(dB + stoff,      bg);
            cp16(dB + stoff + 16, bg + 4);
        }
        CPCOMMIT();

        const uint32_t* As = sm + (size_t)(c & 3) * STW;
        const uint32_t* Bs = As + CHW;

        uint4 bq[4];
        #pragma unroll
        for (int j = 0; j < 4; j++)
            bq[j] = *(const uint4*)(Bs + (wn * 4 + j) * 128 + lane * 4);

        #pragma unroll
        for (int s8 = 0; s8 < 2; s8++) {
            uint4 aq[4];
            #pragma unroll
            for (int i = 0; i < 4; i++)
                aq[i] = *(const uint4*)(As + s8 * 1024 + (wm * 4 + i) * 128
                                        + lane * 4);
            #pragma unroll
            for (int i = 0; i < 4; i++)
                #pragma unroll
                for (int j = 0; j < 4; j++) {
                    const uint32_t b0 = s8 ? bq[j].z : bq[j].x;
                    const uint32_t b1 = s8 ? bq[j].w : bq[j].y;
                    mma_tf32(acc[i][j], aq[i].x, aq[i].y, aq[i].z, aq[i].w,
                             b0, b1);
                }
        }
    }

    // ---- epilogue ----
    if (mode == 0) {
        #pragma unroll
        for (int i = 0; i < 4; i++) {
            const int row0 = by * 128 + wm * 64 + i * 16 + gid;
            #pragma unroll
            for (int j = 0; j < 4; j++) {
                const int col = bx * 128 + wn * 32 + j * 8 + 2 * tig;
                float b0 = 0.0f, b1 = 0.0f;
                if (bias != nullptr) { b0 = bias[col]; b1 = bias[col + 1]; }
                float2 v0 = make_float2(acc[i][j][0] + b0, acc[i][j][1] + b1);
                float2 v1 = make_float2(acc[i][j][2] + b0, acc[i][j][3] + b1);
                *(float2*)(C + (size_t)row0 * E_ + col) = v0;
                *(float2*)(C + (size_t)(row0 + 8) * E_ + col) = v1;
            }
        }
    } else {
        uint32_t* Cb = (uint32_t*)C;
        #pragma unroll
        for (int i = 0; i < 4; i++) {
            const int row0 = by * 128 + wm * 64 + i * 16 + gid;
            #pragma unroll
            for (int j = 0; j < 4; j++) {
                const int col = bx * 128 + wn * 32 + j * 8 + 2 * tig;
                #pragma unroll
                for (int f = 0; f < 4; f++) {
                    const int m = row0 + (f >> 1) * 8;
                    const int n = col + (f & 1);
                    float v = acc[i][j][f];
                    size_t adr;
                    if (mode == 1) { v *= QSCALE; adr = q_addr(m, n); }
                    else if (mode == 2) { adr = k_addr(m, n); }
                    else { adr = v_addr(m, n); }
                    Cb[adr] = f2tf(v);
                }
            }
        }
    }
}

// ---------------------------------------------------------------------------
// TF32 tensor-core flash attention, fragment-order operands.
// Block = 128 threads (4 warps) = 64 query rows; grid (S/64, GROUPS).
// K/V chunks (4096 words each) staged linearly via cp.async double buffer;
// all fragment gathers are LDS.128 / LDG.128. Softmax in exp2 domain
// (scale*log2e pre-folded into Q by the QKV GEMM).
// ---------------------------------------------------------------------------
#define ACH 4096                    // words per chunk per operand
#define ABUF (2 * ACH)              // words per stage (K+V)
#define ATT_SMEM (2 * ABUF * 4)     // 65536 bytes

__global__ __launch_bounds__(128, 3) void attn_mma()
{
    extern __shared__ uint32_t ash[];
    const uint32_t sb = smem_u32(ash);

    const int g    = blockIdx.y;
    const int tid  = threadIdx.x;
    const int lane = tid & 31;
    const int w    = tid >> 5;
    const int gid  = lane >> 2;
    const int tig  = lane & 3;

    const uint32_t* Kf = g_kb + (size_t)g * 65536;
    const uint32_t* Vf = g_vb + (size_t)g * 65536;
    const uint32_t* Qf = g_qb + (size_t)g * 65536
                       + (size_t)(blockIdx.x * 4 + w) * 1024;

    // ---- stage chunk 0 (K then V, fully linear) ----
    #pragma unroll
    for (int it = 0; it < 8; it++) {
        const int sl = tid + it * 128;          // 16B slot 0..1023
        cp16(sb + sl * 16,           Kf + sl * 4);
        cp16(sb + ACH * 4 + sl * 16, Vf + sl * 4);
    }
    CPCOMMIT();

    // ---- Q fragments straight from gmem (coalesced LDG.128) ----
    uint4 qf[8];
    #pragma unroll
    for (int kd = 0; kd < 8; kd++)
        qf[kd] = *(const uint4*)(Qf + kd * 128 + lane * 4);

    CPWAIT(0);
    __syncthreads();

    float oacc[8][4];
    #pragma unroll
    for (int jd = 0; jd < 8; jd++)
        #pragma unroll
        for (int f = 0; f < 4; f++) oacc[jd][f] = 0.0f;

    float m0 = -1e30f, m1 = -1e30f, l0 = 0.0f, l1 = 0.0f;

    const int srcbase = lane & ~3;
    const int src0 = srcbase | (tig >> 1);
    const int src2 = src0 + 2;
    const bool hi = tig & 1;

    for (int c = 0; c < 16; c++) {
        if (c > 0) { CPWAIT(0); __syncthreads(); }

        if (c + 1 < 16) {
            const uint32_t dstb = sb + (uint32_t)(((c + 1) & 1) * ABUF) * 4;
            const int base = (c + 1) * ACH;
            #pragma unroll
            for (int it = 0; it < 8; it++) {
                const int sl = tid + it * 128;
                cp16(dstb + sl * 16,           Kf + base + sl * 4);
                cp16(dstb + ACH * 4 + sl * 16, Vf + base + sl * 4);
            }
        }
        CPCOMMIT();

        const uint32_t* Ks = ash + (size_t)(c & 1) * ABUF;
        const uint32_t* Vs = Ks + ACH;

        // ---- S = Q @ K^T : per key-tile jt, 4 LDS.128 + 8 mma ----
        float sacc[8][4];
        #pragma unroll
        for (int j = 0; j < 8; j++)
            #pragma unroll
            for (int f = 0; f < 4; f++) sacc[j][f] = 0.0f;

        #pragma unroll
        for (int jt = 0; jt < 8; jt++) {
            uint4 kq[4];
            #pragma unroll
            for (int q = 0; q < 4; q++)
                kq[q] = *(const uint4*)(Ks + jt * 512 + q * 128 + lane * 4);
            #pragma unroll
            for (int q = 0; q < 4; q++) {
                mma_tf32(sacc[jt], qf[2 * q].x, qf[2 * q].y,
                         qf[2 * q].z, qf[2 * q].w, kq[q].x, kq[q].y);
                mma_tf32(sacc[jt], qf[2 * q + 1].x, qf[2 * q + 1].y,
                         qf[2 * q + 1].z, qf[2 * q + 1].w, kq[q].z, kq[q].w);
            }
        }

        // ---- online softmax (exp2 domain; scores already * log2e/32) ----
        float mx0 = -1e30f, mx1 = -1e30f;
        #pragma unroll
        for (int j = 0; j < 8; j++) {
            mx0 = fmaxf(mx0, fmaxf(sacc[j][0], sacc[j][1]));
            mx1 = fmaxf(mx1, fmaxf(sacc[j][2], sacc[j][3]));
        }
        mx0 = fmaxf(mx0, __shfl_xor_sync(FULL, mx0, 1));
        mx0 = fmaxf(mx0, __shfl_xor_sync(FULL, mx0, 2));
        mx1 = fmaxf(mx1, __shfl_xor_sync(FULL, mx1, 1));
        mx1 = fmaxf(mx1, __shfl_xor_sync(FULL, mx1, 2));

        const float nm0 = fmaxf(m0, mx0);
        const float nm1 = fmaxf(m1, mx1);
        const float a0 = ex2f(m0 - nm0);
        const float a1 = ex2f(m1 - nm1);
        m0 = nm0; m1 = nm1;

        float rs0 = 0.0f, rs1 = 0.0f;
        #pragma unroll
        for (int j = 0; j < 8; j++) {
            sacc[j][0] = ex2f(sacc[j][0] - nm0);
            sacc[j][1] = ex2f(sacc[j][1] - nm0);
            sacc[j][2] = ex2f(sacc[j][2] - nm1);
            sacc[j][3] = ex2f(sacc[j][3] - nm1);
            rs0 += sacc[j][0] + sacc[j][1];
            rs1 += sacc[j][2] + sacc[j][3];
        }
        rs0 += __shfl_xor_sync(FULL, rs0, 1);
        rs0 += __shfl_xor_sync(FULL, rs0, 2);
        rs1 += __shfl_xor_sync(FULL, rs1, 1);
        rs1 += __shfl_xor_sync(FULL, rs1, 2);
        l0 = l0 * a0 + rs0;
        l1 = l1 * a1 + rs1;

        #pragma unroll
        for (int jd = 0; jd < 8; jd++) {
            oacc[jd][0] *= a0; oacc[jd][1] *= a0;
            oacc[jd][2] *= a1; oacc[jd][3] *= a1;
        }

        // ---- O += P @ V : per kk-pair, build P A-frags (shfl) then 8 jd ----
        #pragma unroll
        for (int p = 0; p < 4; p++) {
            uint32_t af0[4], af1[4];
            #pragma unroll
            for (int h = 0; h < 2; h++) {
                const int kk = 2 * p + h;
                const float p0 = sacc[kk][0], p1 = sacc[kk][1];
                const float p2 = sacc[kk][2], p3 = sacc[kk][3];
                const float x00 = __shfl_sync(FULL, p0, src0);
                const float x01 = __shfl_sync(FULL, p1, src0);
                const float x20 = __shfl_sync(FULL, p2, src0);
                const float x21 = __shfl_sync(FULL, p3, src0);
                const float y00 = __shfl_sync(FULL, p0, src2);
                const float y01 = __shfl_sync(FULL, p1, src2);
                const float y20 = __shfl_sync(FULL, p2, src2);
                const float y21 = __shfl_sync(FULL, p3, src2);
                uint32_t* af = h ? af1 : af0;
                af[0] = f2tf(hi ? x01 : x00);
                af[1] = f2tf(hi ? x21 : x20);
                af[2] = f2tf(hi ? y01 : y00);
                af[3] = f2tf(hi ? y21 : y20);
            }
            #pragma unroll
            for (int jd = 0; jd < 8; jd++) {
                uint4 vq = *(const uint4*)(Vs + jd * 512 + p * 128 + lane * 4);
                mma_tf32(oacc[jd], af0[0], af0[1], af0[2], af0[3], vq.x, vq.y);
                mma_tf32(oacc[jd], af1[0], af1[1], af1[2], af1[3], vq.z, vq.w);
            }
        }
    }

    // ---- epilogue: normalize, write tf32 bits into GEMM A-frag layout ----
    const float inv0 = 1.0f / l0;
    const float inv1 = 1.0f / l1;
    const int b = g >> 4, h = g & 15;
    const int mr0 = b * S_ + blockIdx.x * 64 + w * 16 + gid;
    const int mr1 = mr0 + 8;
    #pragma unroll
    for (int jd = 0; jd < 8; jd++) {
        const int col = h * D_ + 8 * jd + 2 * tig;
        g_attb[a_addr(mr0, col)]     = f2tf(oacc[jd][0] * inv0);
        g_attb[a_addr(mr0, col + 1)] = f2tf(oacc[jd][1] * inv0);
        g_attb[a_addr(mr1, col)]     = f2tf(oacc[jd][2] * inv1);
        g_attb[a_addr(mr1, col + 1)] = f2tf(oacc[jd][3] * inv1);
    }
}

// ---------------------------------------------------------------------------
extern "C" void kernel_launch(void* const* d_in, const int* in_sizes, int n_in,
                              void* d_out, int out_size)
{
    const float* hs    = (const float*)d_in[0];
    const float* w_q   = (const float*)d_in[1];
    const float* w_k   = (const float*)d_in[2];
    const float* w_v   = (const float*)d_in[3];
    const float* w_out = (const float*)d_in[4];
    const float* b_out = (const float*)d_in[5];
    float* out = (float*)d_out;

    uint32_t *qp, *kp, *vp, *wtp, *xp, *abp;
    cudaGetSymbolAddress((void**)&qp, g_qb);
    cudaGetSymbolAddress((void**)&kp, g_kb);
    cudaGetSymbolAddress((void**)&vp, g_vb);
    cudaGetSymbolAddress((void**)&abp, g_attb);
    cudaGetSymbolAddress((void**)&xp, g_x);
    cudaGetSymbolAddress((void**)&wtp, g_wt);

    cudaFuncSetAttribute(gemm_tc32, cudaFuncAttributeMaxDynamicSharedMemorySize,
                         GSMEM);
    cudaFuncSetAttribute(attn_mma, cudaFuncAttributeMaxDynamicSharedMemorySize,
                         ATT_SMEM);

    // 1. one-time operand conversion into fragment-order layouts
    transpose_w<<<dim3(1024, 1, 4), 256>>>(w_q, w_k, w_v, w_out, wtp);
    convert_x<<<ROWS * E_ / 1024, 256>>>(hs, xp);

    // 2. fused QKV projections (scatter into attention frag layouts)
    gemm_tc32<<<dim3(8, 64, 3), 256, GSMEM>>>(
        xp, wtp, nullptr, 1, (float*)qp, (float*)kp, (float*)vp);

    // 3. attention (frag-order in, GEMM A-frag out)
    attn_mma<<<dim3(S_ / 64, GROUPS), 128, ATT_SMEM>>>();

    // 4. output projection (fp32 out + bias)
    gemm_tc32<<<dim3(8, 64, 1), 256, GSMEM>>>(
        abp, wtp + (size_t)3 * E_ * E_, b_out, 0, out, out, out);
}